// round 1
// baseline (speedup 1.0000x reference)
#include <cuda_runtime.h>

#define BATCH 8
#define SEQ   4096
#define HID   1024
// 4096 = 64 x 64 four-step decomposition

// Twiddle table W_4096^j = exp(-2*pi*i*j/4096)
__device__ float2 g_tw4096[4096];
// Scratch: Y[b][n2][k1][h] complex, 8*64*64*1024 float2 = 268 MB
__device__ float2 g_scratch[(size_t)BATCH * SEQ * HID];

__global__ void init_tw_kernel() {
    int j = blockIdx.x * blockDim.x + threadIdx.x;
    if (j < 4096) {
        float s, c;
        sincospif(-(float)j / 2048.0f, &s, &c);  // angle = -2*pi*j/4096
        g_tw4096[j] = make_float2(c, s);
    }
}

// Bit-reverse of 6-bit value (compile-time)
__device__ __forceinline__ constexpr int rev6(int x) {
    return ((x & 1) << 5) | ((x & 2) << 3) | ((x & 4) << 1) |
           ((x & 8) >> 1) | ((x & 16) >> 3) | ((x & 32) >> 5);
}

// W_64^j = exp(-2*pi*i*j/64), j in [0,32). Literal constants -> FFMA immediates.
__device__ __forceinline__ float tw64_re(int j) {
    constexpr float c[32] = {
        1.00000000000f, 0.99518472667f, 0.98078528040f, 0.95694033573f,
        0.92387953251f, 0.88192126435f, 0.83146961230f, 0.77301045336f,
        0.70710678119f, 0.63439328416f, 0.55557023302f, 0.47139673683f,
        0.38268343236f, 0.29028467725f, 0.19509032202f, 0.09801714033f,
        0.00000000000f,-0.09801714033f,-0.19509032202f,-0.29028467725f,
       -0.38268343236f,-0.47139673683f,-0.55557023302f,-0.63439328416f,
       -0.70710678119f,-0.77301045336f,-0.83146961230f,-0.88192126435f,
       -0.92387953251f,-0.95694033573f,-0.98078528040f,-0.99518472667f };
    return c[j];
}
__device__ __forceinline__ float tw64_im(int j) {
    // -sin(2*pi*j/64)
    constexpr float s[32] = {
       -0.00000000000f,-0.09801714033f,-0.19509032202f,-0.29028467725f,
       -0.38268343236f,-0.47139673683f,-0.55557023302f,-0.63439328416f,
       -0.70710678119f,-0.77301045336f,-0.83146961230f,-0.88192126435f,
       -0.92387953251f,-0.95694033573f,-0.98078528040f,-0.99518472667f,
       -1.00000000000f,-0.99518472667f,-0.98078528040f,-0.95694033573f,
       -0.92387953251f,-0.88192126435f,-0.83146961230f,-0.77301045336f,
       -0.70710678119f,-0.63439328416f,-0.55557023302f,-0.47139673683f,
       -0.38268343236f,-0.29028467725f,-0.19509032202f,-0.09801714033f };
    return s[j];
}

// In-register 64-point DIF radix-2 FFT. Output is bit-reversed:
// after return, X[k] = re[rev6(k)], im[rev6(k)].
__device__ __forceinline__ void fft64(float (&re)[64], float (&im)[64]) {
#pragma unroll
    for (int stage = 0; stage < 6; stage++) {
        const int s = 32 >> stage;
#pragma unroll
        for (int j = 0; j < 64; j += 2 * s) {
#pragma unroll
            for (int t = 0; t < s; t++) {
                const int a = j + t;
                const int b = a + s;
                float ar = re[a], ai = im[a];
                float br = re[b], bi = im[b];
                re[a] = ar + br;
                im[a] = ai + bi;
                float dr = ar - br, di = ai - bi;
                const int ti = t << stage;  // twiddle W_64^{t<<stage}
                float wr = tw64_re(ti), wi = tw64_im(ti);
                re[b] = dr * wr - di * wi;
                im[b] = dr * wi + di * wr;
            }
        }
    }
}

// Kernel 1: per (b, n2, h): A[k1] = sum_n1 x[64*n1+n2] W_64^{n1 k1},
// then Y[b][n2][k1][h] = A[k1] * W_4096^{n2*k1}
__global__ void __launch_bounds__(128) fft_pass1(const float* __restrict__ x) {
    const int h  = blockIdx.x * 128 + threadIdx.x;  // gridDim.x = HID/128 = 8
    const int n2 = blockIdx.y;                      // 64
    const int b  = blockIdx.z;                      // 8

    const float* xp = x + ((size_t)b * SEQ + n2) * HID + h;
    float re[64], im[64];
#pragma unroll
    for (int n1 = 0; n1 < 64; n1++) {
        re[n1] = xp[(size_t)n1 * 64 * HID];
        im[n1] = 0.0f;
    }
    fft64(re, im);

    float2* yp = g_scratch + ((size_t)(b * 64 + n2) * 64) * HID + h;
#pragma unroll
    for (int k1 = 0; k1 < 64; k1++) {
        float vr = re[rev6(k1)], vi = im[rev6(k1)];
        float2 w = g_tw4096[n2 * k1];  // warp-uniform index -> broadcast
        yp[(size_t)k1 * HID] = make_float2(vr * w.x - vi * w.y,
                                           vr * w.y + vi * w.x);
    }
}

// Kernel 2: per (b, k1, h): X[k1 + 64*k2] = sum_n2 Y[n2][k1] W_64^{n2 k2};
// write real part * (1/64)  (ortho norm 1/sqrt(4096)).
__global__ void __launch_bounds__(128) fft_pass2(float* __restrict__ out) {
    const int h  = blockIdx.x * 128 + threadIdx.x;
    const int k1 = blockIdx.y;
    const int b  = blockIdx.z;

    const float2* yp = g_scratch + ((size_t)(b * 64) * 64 + k1) * HID + h;
    float re[64], im[64];
#pragma unroll
    for (int n2 = 0; n2 < 64; n2++) {
        float2 v = yp[(size_t)n2 * 64 * HID];
        re[n2] = v.x;
        im[n2] = v.y;
    }
    fft64(re, im);

    float* op = out + ((size_t)b * SEQ + k1) * HID + h;
    const float scale = 1.0f / 64.0f;
#pragma unroll
    for (int k2 = 0; k2 < 64; k2++) {
        op[(size_t)k2 * 64 * HID] = re[rev6(k2)] * scale;
    }
}

extern "C" void kernel_launch(void* const* d_in, const int* in_sizes, int n_in,
                              void* d_out, int out_size) {
    const float* x = (const float*)d_in[0];
    float* out = (float*)d_out;

    init_tw_kernel<<<16, 256>>>();
    dim3 grid(HID / 128, 64, BATCH);
    fft_pass1<<<grid, 128>>>(x);
    fft_pass2<<<grid, 128>>>(out);
}

// round 2
// speedup vs baseline: 1.3969x; 1.3969x over previous
#include <cuda_runtime.h>
#include <cuda_fp16.h>

#define BATCH 8
#define SEQ   4096
#define HID   1024
#define K1N   33   // Hermitian: store only k1 = 0..32 of 64

// Twiddle table W_4096^j = exp(-2*pi*i*j/4096), j < 64*32+1
__device__ float2 g_tw4096[4096];
// Scratch: Y[b][n2][k1(0..32)][h] as half2(re,im): 8*64*33*1024*4B = 69 MB
__device__ __half2 g_scratch[(size_t)BATCH * 64 * K1N * HID];

__global__ void init_tw_kernel() {
    int j = blockIdx.x * blockDim.x + threadIdx.x;
    if (j < 4096) {
        float s, c;
        sincospif(-(float)j / 2048.0f, &s, &c);  // angle = -2*pi*j/4096
        g_tw4096[j] = make_float2(c, s);
    }
}

// Bit-reverse of 6-bit value (compile-time in unrolled loops)
__device__ __forceinline__ constexpr int rev6(int x) {
    return ((x & 1) << 5) | ((x & 2) << 3) | ((x & 4) << 1) |
           ((x & 8) >> 1) | ((x & 16) >> 3) | ((x & 32) >> 5);
}

// W_64^j, j in [0,32). Literal constants -> FFMA immediates.
__device__ __forceinline__ float tw64_re(int j) {
    constexpr float c[32] = {
        1.00000000000f, 0.99518472667f, 0.98078528040f, 0.95694033573f,
        0.92387953251f, 0.88192126435f, 0.83146961230f, 0.77301045336f,
        0.70710678119f, 0.63439328416f, 0.55557023302f, 0.47139673683f,
        0.38268343236f, 0.29028467725f, 0.19509032202f, 0.09801714033f,
        0.00000000000f,-0.09801714033f,-0.19509032202f,-0.29028467725f,
       -0.38268343236f,-0.47139673683f,-0.55557023302f,-0.63439328416f,
       -0.70710678119f,-0.77301045336f,-0.83146961230f,-0.88192126435f,
       -0.92387953251f,-0.95694033573f,-0.98078528040f,-0.99518472667f };
    return c[j];
}
__device__ __forceinline__ float tw64_im(int j) {
    constexpr float s[32] = {
       -0.00000000000f,-0.09801714033f,-0.19509032202f,-0.29028467725f,
       -0.38268343236f,-0.47139673683f,-0.55557023302f,-0.63439328416f,
       -0.70710678119f,-0.77301045336f,-0.83146961230f,-0.88192126435f,
       -0.92387953251f,-0.95694033573f,-0.98078528040f,-0.99518472667f,
       -1.00000000000f,-0.99518472667f,-0.98078528040f,-0.95694033573f,
       -0.92387953251f,-0.88192126435f,-0.83146961230f,-0.77301045336f,
       -0.70710678119f,-0.63439328416f,-0.55557023302f,-0.47139673683f,
       -0.38268343236f,-0.29028467725f,-0.19509032202f,-0.09801714033f };
    return s[j];
}

// In-register 64-point DIF radix-2 FFT. Output bit-reversed:
// X[k] = re[rev6(k)], im[rev6(k)].
__device__ __forceinline__ void fft64(float (&re)[64], float (&im)[64]) {
#pragma unroll
    for (int stage = 0; stage < 6; stage++) {
        const int s = 32 >> stage;
#pragma unroll
        for (int j = 0; j < 64; j += 2 * s) {
#pragma unroll
            for (int t = 0; t < s; t++) {
                const int a = j + t;
                const int b = a + s;
                float ar = re[a], ai = im[a];
                float br = re[b], bi = im[b];
                re[a] = ar + br;
                im[a] = ai + bi;
                float dr = ar - br, di = ai - bi;
                const int ti = t << stage;
                float wr = tw64_re(ti), wi = tw64_im(ti);
                re[b] = dr * wr - di * wi;
                im[b] = dr * wi + di * wr;
            }
        }
    }
}

// Pass 1: per (b, n2, h): A[k1] = sum_n1 x[64*n1+n2] W_64^{n1 k1},
// Y[b][n2][k1][h] = A[k1] * W_4096^{n2*k1}, stored fp16, k1 = 0..32 only
// (Hermitian: A[64-k1] = conj(A[k1]) since x is real).
__global__ void __launch_bounds__(128) fft_pass1(const float* __restrict__ x) {
    const int h  = blockIdx.x * 128 + threadIdx.x;  // HID/128 = 8
    const int n2 = blockIdx.y;                      // 64
    const int b  = blockIdx.z;                      // 8

    const float* xp = x + ((size_t)b * SEQ + n2) * HID + h;
    float re[64], im[64];
#pragma unroll
    for (int n1 = 0; n1 < 64; n1++) {
        re[n1] = xp[(size_t)n1 * 64 * HID];
        im[n1] = 0.0f;
    }
    fft64(re, im);

    __half2* yp = g_scratch + ((size_t)(b * 64 + n2) * K1N) * HID + h;
#pragma unroll
    for (int k1 = 0; k1 < K1N; k1++) {
        float vr = re[rev6(k1)], vi = im[rev6(k1)];
        float2 w = g_tw4096[n2 * k1];  // warp-uniform -> broadcast load
        yp[(size_t)k1 * HID] = __floats2half2_rn(vr * w.x - vi * w.y,
                                                 vr * w.y + vi * w.x);
    }
}

// Pass 2: per (b, k1 in 0..32, h): X[k1 + 64*k2] = sum_n2 Y[n2][k1] W_64^{n2 k2}.
// Write Re*(1/64) for row k1; for k1 in 1..31 also write mirror row 64-k1 via
// Re X[(64-k1)+64*k2] = Re X[k1+64*(63-k2)].
__global__ void __launch_bounds__(128) fft_pass2(float* __restrict__ out) {
    const int h  = blockIdx.x * 128 + threadIdx.x;
    const int k1 = blockIdx.y;                      // 0..32
    const int b  = blockIdx.z;

    const __half2* yp = g_scratch + ((size_t)(b * 64) * K1N + k1) * HID + h;
    float re[64], im[64];
#pragma unroll
    for (int n2 = 0; n2 < 64; n2++) {
        float2 v = __half22float2(yp[(size_t)n2 * K1N * HID]);
        re[n2] = v.x;
        im[n2] = v.y;
    }
    fft64(re, im);

    float* op = out + ((size_t)b * SEQ) * HID + h;
    const float scale = 1.0f / 64.0f;  // ortho norm 1/sqrt(4096)
#pragma unroll
    for (int k2 = 0; k2 < 64; k2++) {
        op[(size_t)(k1 + 64 * k2) * HID] = re[rev6(k2)] * scale;
    }
    if (k1 >= 1 && k1 <= 31) {
        const int k1m = 64 - k1;
#pragma unroll
        for (int k2 = 0; k2 < 64; k2++) {
            op[(size_t)(k1m + 64 * k2) * HID] = re[rev6(63 - k2)] * scale;
        }
    }
}

extern "C" void kernel_launch(void* const* d_in, const int* in_sizes, int n_in,
                              void* d_out, int out_size) {
    const float* x = (const float*)d_in[0];
    float* out = (float*)d_out;

    init_tw_kernel<<<16, 256>>>();
    fft_pass1<<<dim3(HID / 128, 64, BATCH), 128>>>(x);
    fft_pass2<<<dim3(HID / 128, K1N, BATCH), 128>>>(out);
}

// round 3
// speedup vs baseline: 2.1328x; 1.5268x over previous
#include <cuda_runtime.h>
#include <cuda_fp16.h>

#define BATCH 8
#define SEQ   4096
#define HID   1024
#define K1N   33   // Hermitian: store only k1 = 0..32 of 64

// Scratch: Y[b][n2][k1(0..32)][h] as half2(re,im): 8*64*33*1024*4B = 69 MB.
// Fits in the 126 MB L2 — input/output use streaming (.cs) hints so this
// stays resident between pass1 (producer) and pass2 (consumer).
__device__ __half2 g_scratch[(size_t)BATCH * 64 * K1N * HID];

// Bit-reverse of 6-bit value (compile-time in unrolled loops)
__device__ __forceinline__ constexpr int rev6(int x) {
    return ((x & 1) << 5) | ((x & 2) << 3) | ((x & 4) << 1) |
           ((x & 8) >> 1) | ((x & 16) >> 3) | ((x & 32) >> 5);
}

// W_64^j, j in [0,32). Literal constants -> FFMA immediates.
__device__ __forceinline__ float tw64_re(int j) {
    constexpr float c[32] = {
        1.00000000000f, 0.99518472667f, 0.98078528040f, 0.95694033573f,
        0.92387953251f, 0.88192126435f, 0.83146961230f, 0.77301045336f,
        0.70710678119f, 0.63439328416f, 0.55557023302f, 0.47139673683f,
        0.38268343236f, 0.29028467725f, 0.19509032202f, 0.09801714033f,
        0.00000000000f,-0.09801714033f,-0.19509032202f,-0.29028467725f,
       -0.38268343236f,-0.47139673683f,-0.55557023302f,-0.63439328416f,
       -0.70710678119f,-0.77301045336f,-0.83146961230f,-0.88192126435f,
       -0.92387953251f,-0.95694033573f,-0.98078528040f,-0.99518472667f };
    return c[j];
}
__device__ __forceinline__ float tw64_im(int j) {
    constexpr float s[32] = {
       -0.00000000000f,-0.09801714033f,-0.19509032202f,-0.29028467725f,
       -0.38268343236f,-0.47139673683f,-0.55557023302f,-0.63439328416f,
       -0.70710678119f,-0.77301045336f,-0.83146961230f,-0.88192126435f,
       -0.92387953251f,-0.95694033573f,-0.98078528040f,-0.99518472667f,
       -1.00000000000f,-0.99518472667f,-0.98078528040f,-0.95694033573f,
       -0.92387953251f,-0.88192126435f,-0.83146961230f,-0.77301045336f,
       -0.70710678119f,-0.63439328416f,-0.55557023302f,-0.47139673683f,
       -0.38268343236f,-0.29028467725f,-0.19509032202f,-0.09801714033f };
    return s[j];
}

// In-register 64-point DIF radix-2 FFT. Output bit-reversed:
// X[k] = re[rev6(k)], im[rev6(k)].
__device__ __forceinline__ void fft64(float (&re)[64], float (&im)[64]) {
#pragma unroll
    for (int stage = 0; stage < 6; stage++) {
        const int s = 32 >> stage;
#pragma unroll
        for (int j = 0; j < 64; j += 2 * s) {
#pragma unroll
            for (int t = 0; t < s; t++) {
                const int a = j + t;
                const int b = a + s;
                float ar = re[a], ai = im[a];
                float br = re[b], bi = im[b];
                re[a] = ar + br;
                im[a] = ai + bi;
                float dr = ar - br, di = ai - bi;
                const int ti = t << stage;
                float wr = tw64_re(ti), wi = tw64_im(ti);
                re[b] = dr * wr - di * wi;
                im[b] = dr * wi + di * wr;
            }
        }
    }
}

// Pass 1: per (b, n2, h): A[k1] = sum_n1 x[64*n1+n2] W_64^{n1 k1},
// Y[b][n2][k1][h] = A[k1] * W_4096^{n2*k1}, stored fp16, k1 = 0..32 only
// (Hermitian: A[64-k1] = conj(A[k1]) since x is real).
// W_4096^{n2*k1} built by recurrence from one sincospif (no table, no init).
__global__ void __launch_bounds__(128) fft_pass1(const float* __restrict__ x) {
    const int h  = blockIdx.x * 128 + threadIdx.x;  // HID/128 = 8
    const int n2 = blockIdx.y;                      // 64
    const int b  = blockIdx.z;                      // 8

    const float* xp = x + ((size_t)b * SEQ + n2) * HID + h;
    float re[64], im[64];
#pragma unroll
    for (int n1 = 0; n1 < 64; n1++) {
        re[n1] = __ldcs(xp + (size_t)n1 * 64 * HID);  // streaming: don't pollute L2
        im[n1] = 0.0f;
    }
    fft64(re, im);

    // base twiddle W_4096^{n2} = exp(-i*pi*n2/2048)
    float bs, bc;
    sincospif(-(float)n2 / 2048.0f, &bs, &bc);

    __half2* yp = g_scratch + ((size_t)(b * 64 + n2) * K1N) * HID + h;
    float wr = 1.0f, wi = 0.0f;  // W^0
#pragma unroll
    for (int k1 = 0; k1 < K1N; k1++) {
        float vr = re[rev6(k1)], vi = im[rev6(k1)];
        yp[(size_t)k1 * HID] = __floats2half2_rn(vr * wr - vi * wi,
                                                 vr * wi + vi * wr);
        // w *= base  (recurrence: W^{k1+1})
        float nwr = wr * bc - wi * bs;
        float nwi = wr * bs + wi * bc;
        wr = nwr; wi = nwi;
    }
}

// Pass 2: per (b, k1 in 0..32, h): X[k1 + 64*k2] = sum_n2 Y[n2][k1] W_64^{n2 k2}.
// Write Re*(1/64) for row k1; for k1 in 1..31 also write mirror row 64-k1 via
// Re X[(64-k1)+64*k2] = Re X[k1+64*(63-k2)].
__global__ void __launch_bounds__(128) fft_pass2(float* __restrict__ out) {
    const int h  = blockIdx.x * 128 + threadIdx.x;
    const int k1 = blockIdx.y;                      // 0..32
    const int b  = blockIdx.z;

    const __half2* yp = g_scratch + ((size_t)(b * 64) * K1N + k1) * HID + h;
    float re[64], im[64];
#pragma unroll
    for (int n2 = 0; n2 < 64; n2++) {
        float2 v = __half22float2(yp[(size_t)n2 * K1N * HID]);  // want L2 hit
        re[n2] = v.x;
        im[n2] = v.y;
    }
    fft64(re, im);

    float* op = out + ((size_t)b * SEQ) * HID + h;
    const float scale = 1.0f / 64.0f;  // ortho norm 1/sqrt(4096)
#pragma unroll
    for (int k2 = 0; k2 < 64; k2++) {
        __stcs(op + (size_t)(k1 + 64 * k2) * HID, re[rev6(k2)] * scale);
    }
    if (k1 >= 1 && k1 <= 31) {
        const int k1m = 64 - k1;
#pragma unroll
        for (int k2 = 0; k2 < 64; k2++) {
            __stcs(op + (size_t)(k1m + 64 * k2) * HID, re[rev6(63 - k2)] * scale);
        }
    }
}

extern "C" void kernel_launch(void* const* d_in, const int* in_sizes, int n_in,
                              void* d_out, int out_size) {
    const float* x = (const float*)d_in[0];
    float* out = (float*)d_out;

    fft_pass1<<<dim3(HID / 128, 64, BATCH), 128>>>(x);
    fft_pass2<<<dim3(HID / 128, K1N, BATCH), 128>>>(out);
}